// round 9
// baseline (speedup 1.0000x reference)
#include <cuda_runtime.h>
#include <cuda_bf16.h>
#include <math.h>
#include <stdint.h>

#define BATCH   2
#define SEQ     2048
#define DMODEL  1024
#define NHEADS  16
#define DHEAD   64
#define MTOT    (BATCH*SEQ)   // 4096
#define NELEM   (MTOT*DMODEL) // 4194304

// ---------------- scratch (__device__ globals; no allocs allowed) ----------
__device__ float          g_Q[NELEM];
__device__ float          g_K[NELEM];
__device__ __nv_bfloat16  g_Hh[NELEM],  g_Hl[NELEM];
__device__ __nv_bfloat16  g_Wh[1024*3072], g_Wl[1024*3072];
__device__ __nv_bfloat16  g_Woh[1024*1024], g_Wol[1024*1024];
__device__ __nv_bfloat16  g_Qh[NELEM], g_Ql[NELEM];
__device__ __nv_bfloat16  g_Kh[NELEM], g_Kl[NELEM];
__device__ __nv_bfloat16  g_Vh[NELEM], g_Vl[NELEM];
__device__ __nv_bfloat16  g_Oh[NELEM], g_Ol[NELEM];

// ---------------- helpers ---------------------------------------------------
__device__ __forceinline__ unsigned bfpack(float a, float b) {
    __nv_bfloat162 h = __floats2bfloat162_rn(a, b);
    return *reinterpret_cast<unsigned*>(&h);
}
__device__ __forceinline__ void bfsplit2(float a, float b, unsigned &hi, unsigned &lo) {
    float ha = __bfloat162float(__float2bfloat16_rn(a));
    float hb = __bfloat162float(__float2bfloat16_rn(b));
    hi = bfpack(ha, hb);
    lo = bfpack(a - ha, b - hb);
}
__device__ __forceinline__ void bfsplit1(float a, __nv_bfloat16 &hi, __nv_bfloat16 &lo) {
    hi = __float2bfloat16_rn(a);
    lo = __float2bfloat16_rn(a - __bfloat162float(hi));
}

__device__ __forceinline__ void mma_bf16(float c[4], const unsigned a[4], const unsigned b[2]) {
    asm volatile(
        "mma.sync.aligned.m16n8k16.row.col.f32.bf16.bf16.f32 "
        "{%0,%1,%2,%3}, {%4,%5,%6,%7}, {%8,%9}, {%0,%1,%2,%3};\n"
        : "+f"(c[0]), "+f"(c[1]), "+f"(c[2]), "+f"(c[3])
        : "r"(a[0]), "r"(a[1]), "r"(a[2]), "r"(a[3]), "r"(b[0]), "r"(b[1]));
}
__device__ __forceinline__ void ldmx4(unsigned &d0, unsigned &d1, unsigned &d2, unsigned &d3,
                                      uint32_t addr) {
    asm volatile("ldmatrix.sync.aligned.m8n8.x4.shared.b16 {%0,%1,%2,%3}, [%4];"
                 : "=r"(d0), "=r"(d1), "=r"(d2), "=r"(d3) : "r"(addr));
}
__device__ __forceinline__ void ldmx2t(unsigned &d0, unsigned &d1, uint32_t addr) {
    asm volatile("ldmatrix.sync.aligned.m8n8.x2.trans.shared.b16 {%0,%1}, [%2];"
                 : "=r"(d0), "=r"(d1) : "r"(addr));
}
__device__ __forceinline__ void cp_async16(uint32_t dst, const void* src) {
    asm volatile("cp.async.cg.shared.global [%0], [%1], 16;" :: "r"(dst), "l"(src));
}

// ---------------------------------------------------------------------------
// split_all: hidden -> Hh/Hl ; Wq|Wk|Wv -> fused Wh/Wl [1024][3072] ; Wo -> Woh/Wol
// One thread = one float2 pair. 4M threads total.
// ---------------------------------------------------------------------------
__global__ void split_all(const float* __restrict__ H,
                          const float* __restrict__ Wq, const float* __restrict__ Wk,
                          const float* __restrict__ Wv, const float* __restrict__ Wo,
                          __nv_bfloat16* __restrict__ Hh, __nv_bfloat16* __restrict__ Hl,
                          __nv_bfloat16* __restrict__ Wh, __nv_bfloat16* __restrict__ Wl,
                          __nv_bfloat16* __restrict__ Woh, __nv_bfloat16* __restrict__ Wol)
{
    int idx = blockIdx.x * blockDim.x + threadIdx.x;      // [0, 4194304)
    unsigned hi, lo;
    if (idx < 2097152) {                                  // hidden pairs
        int e0 = idx * 2;
        float2 v = *(const float2*)(H + e0);
        bfsplit2(v.x, v.y, hi, lo);
        *(unsigned*)(Hh + e0) = hi;
        *(unsigned*)(Hl + e0) = lo;
    } else if (idx < 3670016) {                           // Wq/Wk/Wv pairs
        int p = idx - 2097152;
        int which = p >> 19;                              // 0,1,2
        int q = p & 524287;
        int r = q >> 9;
        int c2 = (q & 511) * 2;
        const float* W = (which == 0) ? Wq : (which == 1) ? Wk : Wv;
        float2 v = *(const float2*)(W + r * 1024 + c2);
        bfsplit2(v.x, v.y, hi, lo);
        int dst = r * 3072 + which * 1024 + c2;
        *(unsigned*)(Wh + dst) = hi;
        *(unsigned*)(Wl + dst) = lo;
    } else {                                              // Wo pairs
        int p = idx - 3670016;
        int r = p >> 9;
        int c2 = (p & 511) * 2;
        float2 v = *(const float2*)(Wo + r * 1024 + c2);
        bfsplit2(v.x, v.y, hi, lo);
        *(unsigned*)(Woh + r * 1024 + c2) = hi;
        *(unsigned*)(Wol + r * 1024 + c2) = lo;
    }
}

// ---------------------------------------------------------------------------
// bf16 3-term split GEMM: C = A @ B. A planes [M][K] row-major, B planes [K][N].
// 128x128x32 CTA tile, 8 warps (warp 64x32), cp.async double-buffered.
// Fragments via ldmatrix (A: x4 row-major stride 40, B: x2.trans stride 136).
// QKV=true: N=3072; cols<1024 -> Cq fp32, <2048 -> Ck fp32, else split->Vh/Vl.
// ---------------------------------------------------------------------------
#define GEMM_SMEM (2 * 37888)

template<bool QKV>
__global__ __launch_bounds__(256, 2)
void gemm_bf16s(const __nv_bfloat16* __restrict__ Ah, const __nv_bfloat16* __restrict__ Al,
                const __nv_bfloat16* __restrict__ Bh, const __nv_bfloat16* __restrict__ Bl,
                float* __restrict__ C, float* __restrict__ Cq, float* __restrict__ Ck,
                __nv_bfloat16* __restrict__ Vh, __nv_bfloat16* __restrict__ Vl,
                int M, int N, int K)
{
    extern __shared__ __nv_bfloat16 gsm[];

    const int tid  = threadIdx.x;
    const int lane = tid & 31;
    const int warp = tid >> 5;
    const int rowW = (warp >> 2) * 64;
    const int colW = (warp & 3) * 32;
    const int qr   = lane >> 2;
    const int qc   = lane & 3;
    const int l15  = lane & 15;
    const int hi8  = (lane >> 4) << 3;

    const int rowBase = blockIdx.y * 128;
    const int colBase = blockIdx.x * 128;

    const uint32_t sbase = (uint32_t)__cvta_generic_to_shared(gsm);
    const __nv_bfloat16* Aps[2] = {Ah, Al};
    const __nv_bfloat16* Bps[2] = {Bh, Bl};

    auto stage = [&](int buf, int k0) {
        uint32_t base = sbase + (uint32_t)buf * 37888u;
        #pragma unroll
        for (int l = 0; l < 4; l++) {                     // A: 1024 chunks
            int c = tid + l * 256;
            int plane = c >> 9;
            int r = (c >> 2) & 127;
            int col8 = (c & 3) << 3;
            cp_async16(base + (uint32_t)(plane * 10240 + (r * 40 + col8) * 2),
                       Aps[plane] + (size_t)(rowBase + r) * K + k0 + col8);
        }
        #pragma unroll
        for (int l = 0; l < 4; l++) {                     // B: 1024 chunks
            int c = tid + l * 256;
            int plane = c >> 9;
            int r = (c >> 4) & 31;
            int col8 = (c & 15) << 3;
            cp_async16(base + 20480u + (uint32_t)(plane * 8704 + (r * 136 + col8) * 2),
                       Bps[plane] + (size_t)(k0 + r) * N + colBase + col8);
        }
        asm volatile("cp.async.commit_group;");
    };

    float acc[4][4][4];
    #pragma unroll
    for (int mt = 0; mt < 4; mt++)
        #pragma unroll
        for (int nt = 0; nt < 4; nt++)
            #pragma unroll
            for (int i = 0; i < 4; i++) acc[mt][nt][i] = 0.f;

    stage(0, 0);
    int buf = 0;
    for (int k0 = 0; k0 < K; k0 += 32) {
        asm volatile("cp.async.wait_group 0;");
        __syncthreads();
        if (k0 + 32 < K) stage(buf ^ 1, k0 + 32);

        const uint32_t bb = sbase + (uint32_t)buf * 37888u;

        #pragma unroll
        for (int kk = 0; kk < 2; kk++) {
            // B fragments (2 planes x 4 n-tiles), k16 slab kk
            unsigned bh[4][2], bl[4][2];
            #pragma unroll
            for (int nt = 0; nt < 4; nt++) {
                uint32_t ab = bb + 20480u
                            + (uint32_t)(((kk * 16 + l15) * 136 + colW + nt * 8) * 2);
                ldmx2t(bh[nt][0], bh[nt][1], ab);
                ldmx2t(bl[nt][0], bl[nt][1], ab + 8704u);
            }
            #pragma unroll
            for (int mt = 0; mt < 4; mt++) {
                uint32_t aa = bb
                            + (uint32_t)(((rowW + mt * 16 + l15) * 40 + kk * 16 + hi8) * 2);
                unsigned ah[4], al[4];
                ldmx4(ah[0], ah[1], ah[2], ah[3], aa);
                ldmx4(al[0], al[1], al[2], al[3], aa + 10240u);
                #pragma unroll
                for (int nt = 0; nt < 4; nt++) {
                    mma_bf16(acc[mt][nt], ah, bh[nt]);
                    mma_bf16(acc[mt][nt], ah, bl[nt]);
                    mma_bf16(acc[mt][nt], al, bh[nt]);
                }
            }
        }
        buf ^= 1;
    }

    #pragma unroll
    for (int mt = 0; mt < 4; mt++) {
        int r = rowBase + rowW + mt * 16 + qr;
        #pragma unroll
        for (int nt = 0; nt < 4; nt++) {
            int cg = colBase + colW + nt * 8 + 2 * qc;
            if (!QKV) {
                *(float2*)(C + (size_t)r * N + cg)       = make_float2(acc[mt][nt][0], acc[mt][nt][1]);
                *(float2*)(C + (size_t)(r + 8) * N + cg) = make_float2(acc[mt][nt][2], acc[mt][nt][3]);
            } else {
                if (cg < 1024) {
                    *(float2*)(Cq + (size_t)r * 1024 + cg)       = make_float2(acc[mt][nt][0], acc[mt][nt][1]);
                    *(float2*)(Cq + (size_t)(r + 8) * 1024 + cg) = make_float2(acc[mt][nt][2], acc[mt][nt][3]);
                } else if (cg < 2048) {
                    int c = cg - 1024;
                    *(float2*)(Ck + (size_t)r * 1024 + c)       = make_float2(acc[mt][nt][0], acc[mt][nt][1]);
                    *(float2*)(Ck + (size_t)(r + 8) * 1024 + c) = make_float2(acc[mt][nt][2], acc[mt][nt][3]);
                } else {
                    int c = cg - 2048;
                    unsigned hh, ll;
                    bfsplit2(acc[mt][nt][0], acc[mt][nt][1], hh, ll);
                    *(unsigned*)(Vh + (size_t)r * 1024 + c) = hh;
                    *(unsigned*)(Vl + (size_t)r * 1024 + c) = ll;
                    bfsplit2(acc[mt][nt][2], acc[mt][nt][3], hh, ll);
                    *(unsigned*)(Vh + (size_t)(r + 8) * 1024 + c) = hh;
                    *(unsigned*)(Vl + (size_t)(r + 8) * 1024 + c) = ll;
                }
            }
        }
    }
}

// ---------------------------------------------------------------------------
// RoPE + split: reads fp32 Q,K, writes bf16 hi/lo planes.
// One thread per rotation pair: MTOT*NHEADS*32 = 2,097,152 threads.
// ---------------------------------------------------------------------------
__global__ void rope_split(const float* __restrict__ Q, const float* __restrict__ K,
                           const float* __restrict__ cosT, const float* __restrict__ sinT,
                           __nv_bfloat16* __restrict__ Qh, __nv_bfloat16* __restrict__ Ql,
                           __nv_bfloat16* __restrict__ Kh, __nv_bfloat16* __restrict__ Kl)
{
    int idx = blockIdx.x * blockDim.x + threadIdx.x;
    if (idx >= MTOT * NHEADS * 32) return;
    int d  = idx & 31;
    int h  = (idx >> 5) & (NHEADS - 1);
    int ms = idx >> 9;
    int s  = ms & (SEQ - 1);

    float c  = cosT[s * 32 + d];
    float sn = sinT[s * 32 + d];
    size_t base = (size_t)ms * DMODEL + h * DHEAD + d;

    __nv_bfloat16 hi, lo;

    float x1 = Q[base], x2 = Q[base + 32];
    float r1 = x1 * c - x2 * sn;
    float r2 = x2 * c + x1 * sn;
    bfsplit1(r1, hi, lo); Qh[base] = hi;      Ql[base] = lo;
    bfsplit1(r2, hi, lo); Qh[base + 32] = hi; Ql[base + 32] = lo;

    float y1 = K[base], y2 = K[base + 32];
    r1 = y1 * c - y2 * sn;
    r2 = y2 * c + y1 * sn;
    bfsplit1(r1, hi, lo); Kh[base] = hi;      Kl[base] = lo;
    bfsplit1(r2, hi, lo); Kh[base + 32] = hi; Kl[base + 32] = lo;
}

// ---------------------------------------------------------------------------
// Flash attention, bf16 3-term split, pre-split K/V planes staged via cp.async.
// 64 q-rows/CTA, 4 warps. Smem planes stride 72: KH/KL (alias PH/PL), VH/VL.
// Writes O as hi/lo bf16 planes.
// ---------------------------------------------------------------------------
#define ATTN_SMEM (4 * 4608 * 2)

__global__ __launch_bounds__(128, 4)
void attn_mma(const __nv_bfloat16* __restrict__ Qh, const __nv_bfloat16* __restrict__ Ql,
              const __nv_bfloat16* __restrict__ Khg, const __nv_bfloat16* __restrict__ Klg,
              const __nv_bfloat16* __restrict__ Vhg, const __nv_bfloat16* __restrict__ Vlg,
              __nv_bfloat16* __restrict__ Oh, __nv_bfloat16* __restrict__ Ol)
{
    extern __shared__ __nv_bfloat16 smb[];
    __nv_bfloat16* KH = smb;               // [64][72]  (later PH)
    __nv_bfloat16* KL = smb + 4608;        // [64][72]  (later PL)

    const uint32_t smemB = (uint32_t)__cvta_generic_to_shared(smb);
    const uint32_t vhb = smemB + 2u * 9216u;
    const uint32_t vlb = smemB + 3u * 9216u;

    const int qb = blockIdx.x, h = blockIdx.y, b = blockIdx.z;
    const int tid = threadIdx.x;
    const int lane = tid & 31, w = tid >> 5;
    const int qr = lane >> 2, qc = lane & 3;
    const int rm = w * 16 + qr;
    const int l15 = lane & 15;

    const size_t hoff = (size_t)h * DHEAD;
    const size_t rowQ0 = (size_t)b * SEQ + (size_t)qb * 64;

    // Q fragments from pre-split planes
    unsigned qhi[4][4], qlo[4][4];
    {
        const __nv_bfloat16* qh = Qh + rowQ0 * DMODEL + hoff;
        const __nv_bfloat16* ql = Ql + rowQ0 * DMODEL + hoff;
        #pragma unroll
        for (int ks = 0; ks < 4; ks++) {
            int k = ks * 16;
            qhi[ks][0] = *(const unsigned*)(qh + (size_t)rm * DMODEL + k + 2 * qc);
            qhi[ks][1] = *(const unsigned*)(qh + (size_t)(rm + 8) * DMODEL + k + 2 * qc);
            qhi[ks][2] = *(const unsigned*)(qh + (size_t)rm * DMODEL + k + 8 + 2 * qc);
            qhi[ks][3] = *(const unsigned*)(qh + (size_t)(rm + 8) * DMODEL + k + 8 + 2 * qc);
            qlo[ks][0] = *(const unsigned*)(ql + (size_t)rm * DMODEL + k + 2 * qc);
            qlo[ks][1] = *(const unsigned*)(ql + (size_t)(rm + 8) * DMODEL + k + 2 * qc);
            qlo[ks][2] = *(const unsigned*)(ql + (size_t)rm * DMODEL + k + 8 + 2 * qc);
            qlo[ks][3] = *(const unsigned*)(ql + (size_t)(rm + 8) * DMODEL + k + 8 + 2 * qc);
        }
    }

    float o[8][4];
    #pragma unroll
    for (int nt = 0; nt < 8; nt++)
        #pragma unroll
        for (int i = 0; i < 4; i++) o[nt][i] = 0.f;
    float m0 = -3.0e38f, m1 = -3.0e38f, l0 = 0.f, l1 = 0.f;

    const int rowg0 = qb * 64 + rm;
    const int rowg1 = rowg0 + 8;

    for (int kj = 0; kj <= qb; kj++) {
        // ---- stage K/V hi/lo tiles: raw cp.async copies ----
        const size_t tokOff = ((size_t)b * SEQ + (size_t)kj * 64) * DMODEL + hoff;
        const __nv_bfloat16* srcs[4] = {Khg + tokOff, Klg + tokOff, Vhg + tokOff, Vlg + tokOff};
        #pragma unroll
        for (int l = 0; l < 16; l++) {
            int c = tid + l * 128;
            int plane = c >> 9;
            int r = (c >> 3) & 63;
            int col8 = (c & 7) << 3;
            cp_async16(smemB + (uint32_t)((plane * 4608 + r * 72 + col8) * 2),
                       srcs[plane] + (size_t)r * DMODEL + col8);
        }
        asm volatile("cp.async.commit_group;");
        asm volatile("cp.async.wait_group 0;");
        __syncthreads();

        // ---- S = Q K^T (3-term bf16) ----
        float s[8][4];
        #pragma unroll
        for (int nt = 0; nt < 8; nt++)
            #pragma unroll
            for (int i = 0; i < 4; i++) s[nt][i] = 0.f;

        #pragma unroll
        for (int ks = 0; ks < 4; ks++) {
            const int k = ks * 16;
            #pragma unroll
            for (int nt = 0; nt < 8; nt++) {
                int n = nt * 8 + qr;
                unsigned bh[2], bl[2];
                bh[0] = *(const unsigned*)(KH + n * 72 + k + 2 * qc);
                bh[1] = *(const unsigned*)(KH + n * 72 + k + 8 + 2 * qc);
                bl[0] = *(const unsigned*)(KL + n * 72 + k + 2 * qc);
                bl[1] = *(const unsigned*)(KL + n * 72 + k + 8 + 2 * qc);
                mma_bf16(s[nt], qhi[ks], bh);
                mma_bf16(s[nt], qhi[ks], bl);
                mma_bf16(s[nt], qlo[ks], bh);
            }
        }
        __syncthreads();   // K reads done; KH/KL become PH/PL

        // ---- scale + causal mask + row max ----
        float mx0 = m0, mx1 = m1;
        #pragma unroll
        for (int nt = 0; nt < 8; nt++) {
            int cg = kj * 64 + nt * 8 + 2 * qc;
            #pragma unroll
            for (int d = 0; d < 2; d++) {
                float v0 = s[nt][d] * 0.125f;
                if (cg + d > rowg0) v0 = -1e30f;
                s[nt][d] = v0; mx0 = fmaxf(mx0, v0);
                float v1 = s[nt][2 + d] * 0.125f;
                if (cg + d > rowg1) v1 = -1e30f;
                s[nt][2 + d] = v1; mx1 = fmaxf(mx1, v1);
            }
        }
        mx0 = fmaxf(mx0, __shfl_xor_sync(0xffffffffu, mx0, 1));
        mx0 = fmaxf(mx0, __shfl_xor_sync(0xffffffffu, mx0, 2));
        mx1 = fmaxf(mx1, __shfl_xor_sync(0xffffffffu, mx1, 1));
        mx1 = fmaxf(mx1, __shfl_xor_sync(0xffffffffu, mx1, 2));

        float a0 = __expf(m0 - mx0);
        float a1 = __expf(m1 - mx1);
        m0 = mx0; m1 = mx1;

        float rs0 = 0.f, rs1 = 0.f;
        #pragma unroll
        for (int nt = 0; nt < 8; nt++) {
            float p0 = __expf(s[nt][0] - mx0), p1 = __expf(s[nt][1] - mx0);
            float p2 = __expf(s[nt][2] - mx1), p3 = __expf(s[nt][3] - mx1);
            rs0 += p0 + p1; rs1 += p2 + p3;
            unsigned hh, ll;
            bfsplit2(p0, p1, hh, ll);
            *(unsigned*)(KH + rm * 72 + nt * 8 + 2 * qc) = hh;
            *(unsigned*)(KL + rm * 72 + nt * 8 + 2 * qc) = ll;
            bfsplit2(p2, p3, hh, ll);
            *(unsigned*)(KH + (rm + 8) * 72 + nt * 8 + 2 * qc) = hh;
            *(unsigned*)(KL + (rm + 8) * 72 + nt * 8 + 2 * qc) = ll;
        }
        rs0 += __shfl_xor_sync(0xffffffffu, rs0, 1);
        rs0 += __shfl_xor_sync(0xffffffffu, rs0, 2);
        rs1 += __shfl_xor_sync(0xffffffffu, rs1, 1);
        rs1 += __shfl_xor_sync(0xffffffffu, rs1, 2);
        l0 = l0 * a0 + rs0;
        l1 = l1 * a1 + rs1;

        #pragma unroll
        for (int nt = 0; nt < 8; nt++) {
            o[nt][0] *= a0; o[nt][1] *= a0;
            o[nt][2] *= a1; o[nt][3] *= a1;
        }
        __syncthreads();   // P visible to all warps

        // ---- O += P V (3-term bf16, V frags via ldmatrix.trans) ----
        #pragma unroll
        for (int ks = 0; ks < 4; ks++) {
            const int k = ks * 16;
            unsigned ah[4], al[4];
            ah[0] = *(const unsigned*)(KH + rm * 72 + k + 2 * qc);
            ah[1] = *(const unsigned*)(KH + (rm + 8) * 72 + k + 2 * qc);
            ah[2] = *(const unsigned*)(KH + rm * 72 + k + 8 + 2 * qc);
            ah[3] = *(const unsigned*)(KH + (rm + 8) * 72 + k + 8 + 2 * qc);
            al[0] = *(const unsigned*)(KL + rm * 72 + k + 2 * qc);
            al[1] = *(const unsigned*)(KL + (rm + 8) * 72 + k + 2 * qc);
            al[2] = *(const unsigned*)(KL + rm * 72 + k + 8 + 2 * qc);
            al[3] = *(const unsigned*)(KL + (rm + 8) * 72 + k + 8 + 2 * qc);
            const uint32_t rowOff = (uint32_t)((k + l15) * 72) * 2u;
            #pragma unroll
            for (int nt = 0; nt < 8; nt++) {
                unsigned bh[2], bl[2];
                ldmx2t(bh[0], bh[1], vhb + rowOff + (uint32_t)(nt * 8) * 2u);
                ldmx2t(bl[0], bl[1], vlb + rowOff + (uint32_t)(nt * 8) * 2u);
                mma_bf16(o[nt], ah, bh);
                mma_bf16(o[nt], ah, bl);
                mma_bf16(o[nt], al, bh);
            }
        }
        __syncthreads();   // reads done before next tile staging
    }

    // ---- normalize + split-write O planes ----
    float inv0 = 1.0f / l0, inv1 = 1.0f / l1;
    __nv_bfloat16* oh = Oh + rowQ0 * DMODEL + hoff;
    __nv_bfloat16* ol = Ol + rowQ0 * DMODEL + hoff;
    #pragma unroll
    for (int nt = 0; nt < 8; nt++) {
        int c = nt * 8 + 2 * qc;
        unsigned hh, ll;
        bfsplit2(o[nt][0] * inv0, o[nt][1] * inv0, hh, ll);
        *(unsigned*)(oh + (size_t)rm * DMODEL + c) = hh;
        *(unsigned*)(ol + (size_t)rm * DMODEL + c) = ll;
        bfsplit2(o[nt][2] * inv1, o[nt][3] * inv1, hh, ll);
        *(unsigned*)(oh + (size_t)(rm + 8) * DMODEL + c) = hh;
        *(unsigned*)(ol + (size_t)(rm + 8) * DMODEL + c) = ll;
    }
}

// ---------------------------------------------------------------------------
// Launch
// ---------------------------------------------------------------------------
extern "C" void kernel_launch(void* const* d_in, const int* in_sizes, int n_in,
                              void* d_out, int out_size)
{
    const float* hidden = (const float*)d_in[0];
    const float* cosT   = (const float*)d_in[1];
    const float* sinT   = (const float*)d_in[2];
    // d_in[3] = attention_mask (pure causal; reproduced analytically)
    const float* Wq     = (const float*)d_in[4];
    const float* Wk     = (const float*)d_in[5];
    const float* Wv     = (const float*)d_in[6];
    const float* Wo     = (const float*)d_in[7];
    float* out = (float*)d_out;

    float *Qf, *Kf;
    __nv_bfloat16 *Hh, *Hl, *Wh, *Wl, *Woh, *Wol;
    __nv_bfloat16 *Qh, *Ql, *Kh, *Kl, *Vh, *Vl, *Oh, *Ol;
    cudaGetSymbolAddress((void**)&Qf, g_Q);
    cudaGetSymbolAddress((void**)&Kf, g_K);
    cudaGetSymbolAddress((void**)&Hh, g_Hh);   cudaGetSymbolAddress((void**)&Hl, g_Hl);
    cudaGetSymbolAddress((void**)&Wh, g_Wh);   cudaGetSymbolAddress((void**)&Wl, g_Wl);
    cudaGetSymbolAddress((void**)&Woh, g_Woh); cudaGetSymbolAddress((void**)&Wol, g_Wol);
    cudaGetSymbolAddress((void**)&Qh, g_Qh);   cudaGetSymbolAddress((void**)&Ql, g_Ql);
    cudaGetSymbolAddress((void**)&Kh, g_Kh);   cudaGetSymbolAddress((void**)&Kl, g_Kl);
    cudaGetSymbolAddress((void**)&Vh, g_Vh);   cudaGetSymbolAddress((void**)&Vl, g_Vl);
    cudaGetSymbolAddress((void**)&Oh, g_Oh);   cudaGetSymbolAddress((void**)&Ol, g_Ol);

    cudaFuncSetAttribute(gemm_bf16s<true>,  cudaFuncAttributeMaxDynamicSharedMemorySize, GEMM_SMEM);
    cudaFuncSetAttribute(gemm_bf16s<false>, cudaFuncAttributeMaxDynamicSharedMemorySize, GEMM_SMEM);
    cudaFuncSetAttribute(attn_mma,          cudaFuncAttributeMaxDynamicSharedMemorySize, ATTN_SMEM);

    split_all<<<16384, 256>>>(hidden, Wq, Wk, Wv, Wo, Hh, Hl, Wh, Wl, Woh, Wol);

    gemm_bf16s<true><<<dim3(24, 32), 256, GEMM_SMEM>>>(
        Hh, Hl, Wh, Wl, nullptr, Qf, Kf, Vh, Vl, MTOT, 3072, 1024);

    rope_split<<<8192, 256>>>(Qf, Kf, cosT, sinT, Qh, Ql, Kh, Kl);

    attn_mma<<<dim3(SEQ / 64, NHEADS, BATCH), 128, ATTN_SMEM>>>(
        Qh, Ql, Kh, Kl, Vh, Vl, Oh, Ol);

    gemm_bf16s<false><<<dim3(8, 32), 256, GEMM_SMEM>>>(
        Oh, Ol, Woh, Wol, out, nullptr, nullptr, nullptr, nullptr, MTOT, 1024, 1024);
}

// round 11
// speedup vs baseline: 1.6083x; 1.6083x over previous
#include <cuda_runtime.h>
#include <cuda_bf16.h>
#include <math.h>
#include <stdint.h>

#define BATCH   2
#define SEQ     2048
#define DMODEL  1024
#define NHEADS  16
#define DHEAD   64
#define MTOT    (BATCH*SEQ)   // 4096

// Scratch (allocation-free rule: __device__ globals)
__device__ float g_Q[MTOT*DMODEL];
__device__ float g_K[MTOT*DMODEL];
__device__ float g_V[MTOT*DMODEL];
__device__ float g_O[MTOT*DMODEL];

__device__ __forceinline__ float tf32r(float x) {
    asm("cvt.rna.tf32.f32 %0, %0;" : "+f"(x));
    return x;
}
__device__ __forceinline__ unsigned u32(float x) { return __float_as_uint(x); }

__device__ __forceinline__ void mma_tf32(float c[4], const unsigned a[4], const unsigned b[2]) {
    asm volatile(
        "mma.sync.aligned.m16n8k8.row.col.f32.tf32.tf32.f32 "
        "{%0,%1,%2,%3}, {%4,%5,%6,%7}, {%8,%9}, {%0,%1,%2,%3};\n"
        : "+f"(c[0]), "+f"(c[1]), "+f"(c[2]), "+f"(c[3])
        : "r"(a[0]), "r"(a[1]), "r"(a[2]), "r"(a[3]), "r"(b[0]), "r"(b[1]));
}

__device__ __forceinline__ void mma_bf16(float c[4], const unsigned a[4], const unsigned b[2]) {
    asm volatile(
        "mma.sync.aligned.m16n8k16.row.col.f32.bf16.bf16.f32 "
        "{%0,%1,%2,%3}, {%4,%5,%6,%7}, {%8,%9}, {%0,%1,%2,%3};\n"
        : "+f"(c[0]), "+f"(c[1]), "+f"(c[2]), "+f"(c[3])
        : "r"(a[0]), "r"(a[1]), "r"(a[2]), "r"(a[3]), "r"(b[0]), "r"(b[1]));
}

__device__ __forceinline__ void ldmx2t(unsigned &d0, unsigned &d1, uint32_t addr) {
    asm volatile("ldmatrix.sync.aligned.m8n8.x2.trans.shared.b16 {%0,%1}, [%2];"
                 : "=r"(d0), "=r"(d1) : "r"(addr));
}

__device__ __forceinline__ unsigned bfpack(float a, float b) {
    __nv_bfloat162 h = __floats2bfloat162_rn(a, b);
    return *reinterpret_cast<unsigned*>(&h);
}
__device__ __forceinline__ void bfsplit2(float a, float b, unsigned &hi, unsigned &lo) {
    float ha = __bfloat162float(__float2bfloat16_rn(a));
    float hb = __bfloat162float(__float2bfloat16_rn(b));
    hi = bfpack(ha, hb);
    lo = bfpack(a - ha, b - hb);
}

__device__ __forceinline__ void cp_async16(uint32_t dst, const void* src) {
    asm volatile("cp.async.cg.shared.global [%0], [%1], 16;" :: "r"(dst), "l"(src));
}

// ---------------------------------------------------------------------------
// TF32 GEMM, cp.async double-buffered (proven R4/R5 version).
// ---------------------------------------------------------------------------
#define GEMM_SMEM (2 * (128*36 + 32*136) * 4)

__global__ __launch_bounds__(256, 2)
void gemm_tf32(const float* __restrict__ A, const float* __restrict__ B,
               float* __restrict__ C, int M, int N, int K)
{
    extern __shared__ float gsm[];

    const int tid  = threadIdx.x;
    const int lane = tid & 31;
    const int warp = tid >> 5;
    const int rowW = (warp >> 2) * 64;
    const int colW = (warp & 3) * 32;
    const int qr   = lane >> 2;
    const int qc   = lane & 3;

    const int rowBase = blockIdx.y * 128;
    const int colBase = blockIdx.x * 128;

    const int rA = tid >> 3, cA = (tid & 7) << 2;
    const int rB = tid >> 5, cB = (tid & 31) << 2;

    const uint32_t sbase = (uint32_t)__cvta_generic_to_shared(gsm);

    auto stage = [&](int buf, int k0) {
        uint32_t abuf = sbase + (uint32_t)buf * 8960u * 4u;
        uint32_t bbuf = abuf + 4608u * 4u;
        #pragma unroll
        for (int l = 0; l < 4; l++) {
            int r  = rA + 32 * l;
            cp_async16(abuf + (uint32_t)(r * 36 + cA) * 4u,
                       A + (size_t)(rowBase + r) * K + k0 + cA);
            int rb = rB + 8 * l;
            cp_async16(bbuf + (uint32_t)(rb * 136 + cB) * 4u,
                       B + (size_t)(k0 + rb) * N + colBase + cB);
        }
        asm volatile("cp.async.commit_group;");
    };

    float acc[4][4][4];
    #pragma unroll
    for (int mt = 0; mt < 4; mt++)
        #pragma unroll
        for (int nt = 0; nt < 4; nt++)
            #pragma unroll
            for (int i = 0; i < 4; i++) acc[mt][nt][i] = 0.f;

    stage(0, 0);
    int buf = 0;
    for (int k0 = 0; k0 < K; k0 += 32) {
        asm volatile("cp.async.wait_group 0;");
        __syncthreads();
        if (k0 + 32 < K) stage(buf ^ 1, k0 + 32);

        const float* As = gsm + buf * 8960;
        const float* Bs = As + 4608;

        #pragma unroll
        for (int kk = 0; kk < 4; kk++) {
            const int k = kk * 8;
            unsigned a[4][4], bf[4][2];
            #pragma unroll
            for (int mt = 0; mt < 4; mt++) {
                int r = rowW + mt * 16 + qr;
                a[mt][0] = u32(tf32r(As[r * 36 + k + qc]));
                a[mt][1] = u32(tf32r(As[(r + 8) * 36 + k + qc]));
                a[mt][2] = u32(tf32r(As[r * 36 + k + 4 + qc]));
                a[mt][3] = u32(tf32r(As[(r + 8) * 36 + k + 4 + qc]));
            }
            #pragma unroll
            for (int nt = 0; nt < 4; nt++) {
                int cn = colW + nt * 8 + qr;
                bf[nt][0] = u32(tf32r(Bs[(k + qc) * 136 + cn]));
                bf[nt][1] = u32(tf32r(Bs[(k + 4 + qc) * 136 + cn]));
            }
            #pragma unroll
            for (int mt = 0; mt < 4; mt++)
                #pragma unroll
                for (int nt = 0; nt < 4; nt++)
                    mma_tf32(acc[mt][nt], a[mt], bf[nt]);
        }
        buf ^= 1;
    }

    #pragma unroll
    for (int mt = 0; mt < 4; mt++) {
        int r = rowBase + rowW + mt * 16 + qr;
        #pragma unroll
        for (int nt = 0; nt < 4; nt++) {
            int c = colBase + colW + nt * 8 + 2 * qc;
            *(float2*)(C + (size_t)r * N + c)       = make_float2(acc[mt][nt][0], acc[mt][nt][1]);
            *(float2*)(C + (size_t)(r + 8) * N + c) = make_float2(acc[mt][nt][2], acc[mt][nt][3]);
        }
    }
}

// ---------------------------------------------------------------------------
// RoPE in-place (proven).
// ---------------------------------------------------------------------------
__global__ void rope_kernel(float* __restrict__ Q, float* __restrict__ K,
                            const float* __restrict__ cosT,
                            const float* __restrict__ sinT)
{
    int idx = blockIdx.x * blockDim.x + threadIdx.x;
    int d  = idx & 31;
    int h  = (idx >> 5) & (NHEADS - 1);
    int ms = idx >> 9;
    int s  = ms & (SEQ - 1);

    float c  = cosT[s * 32 + d];
    float sn = sinT[s * 32 + d];
    size_t base = (size_t)ms * DMODEL + h * DHEAD + d;

    float x1 = Q[base], x2 = Q[base + 32];
    Q[base]      = x1 * c - x2 * sn;
    Q[base + 32] = x2 * c + x1 * sn;

    float y1 = K[base], y2 = K[base + 32];
    K[base]      = y1 * c - y2 * sn;
    K[base + 32] = y2 * c + y1 * sn;
}

// ---------------------------------------------------------------------------
// Flash attention: bf16 3-term split, 128 q-rows/CTA (8 warps), 64-token tiles.
// Smem (bf16, stride 72):
//   KH/KL [64][72], VH/VL [64][72], PH/PL [128][72]  -> 73728 B total
// Staging: direct fp32 LDG + inline split (R5-style; proven faster than
// pre-split cp.async). V B-frags via ldmatrix.x2.trans.
// ---------------------------------------------------------------------------
#define ATTN_SMEM (73728)

__global__ __launch_bounds__(256, 2)
void attn_mma(const float* __restrict__ Q, const float* __restrict__ K,
              const float* __restrict__ V, float* __restrict__ O)
{
    extern __shared__ __nv_bfloat16 smb[];
    __nv_bfloat16* KH = smb;               // [64][72]
    __nv_bfloat16* KL = smb + 4608;
    __nv_bfloat16* VH = smb + 2 * 4608;
    __nv_bfloat16* VL = smb + 3 * 4608;
    __nv_bfloat16* PH = smb + 4 * 4608;    // [128][72]
    __nv_bfloat16* PL = PH + 9216;

    const uint32_t smemB = (uint32_t)__cvta_generic_to_shared(smb);
    const uint32_t vhb = smemB + 2u * 9216u;   // byte offsets
    const uint32_t vlb = smemB + 3u * 9216u;

    const int qb = blockIdx.x, h = blockIdx.y, b = blockIdx.z;
    const int tid = threadIdx.x;
    const int lane = tid & 31, w = tid >> 5;   // w: 0..7
    const int qr = lane >> 2, qc = lane & 3;
    const int rm = w * 16 + qr;                // 0..127
    const int l15 = lane & 15;

    const size_t hoff = (size_t)h * DHEAD;
    const size_t rowQ0 = (size_t)b * SEQ + (size_t)qb * 128;

    // ---- Q fragments (bf16 hi/lo), one-time from gmem ----
    unsigned qhi[4][4], qlo[4][4];
    {
        const float* qp = Q + rowQ0 * DMODEL + hoff;
        #pragma unroll
        for (int ks = 0; ks < 4; ks++) {
            int k = ks * 16;
            float2 t;
            t = *(const float2*)(qp + (size_t)rm * DMODEL + k + 2 * qc);
            bfsplit2(t.x, t.y, qhi[ks][0], qlo[ks][0]);
            t = *(const float2*)(qp + (size_t)(rm + 8) * DMODEL + k + 2 * qc);
            bfsplit2(t.x, t.y, qhi[ks][1], qlo[ks][1]);
            t = *(const float2*)(qp + (size_t)rm * DMODEL + k + 8 + 2 * qc);
            bfsplit2(t.x, t.y, qhi[ks][2], qlo[ks][2]);
            t = *(const float2*)(qp + (size_t)(rm + 8) * DMODEL + k + 8 + 2 * qc);
            bfsplit2(t.x, t.y, qhi[ks][3], qlo[ks][3]);
        }
    }

    float o[8][4];
    #pragma unroll
    for (int nt = 0; nt < 8; nt++)
        #pragma unroll
        for (int i = 0; i < 4; i++) o[nt][i] = 0.f;
    float m0 = -3.0e38f, m1 = -3.0e38f, l0 = 0.f, l1 = 0.f;

    const int rowg0 = qb * 128 + rm;
    const int rowg1 = rowg0 + 8;
    const int kjMax = 2 * qb + 1;

    for (int kj = 0; kj <= kjMax; kj++) {
        // ---- stage K/V (64 tokens): fp32 loads + inline split ----
        const float* kp = K + ((size_t)b * SEQ + (size_t)kj * 64) * DMODEL + hoff;
        const float* vp = V + ((size_t)b * SEQ + (size_t)kj * 64) * DMODEL + hoff;
        #pragma unroll
        for (int l = 0; l < 4; l++) {
            int idx = tid + l * 256;
            int r = idx >> 4, c = (idx & 15) << 2;
            float4 kv = *(const float4*)(kp + (size_t)r * DMODEL + c);
            unsigned hA, lA, hB, lB;
            bfsplit2(kv.x, kv.y, hA, lA);
            bfsplit2(kv.z, kv.w, hB, lB);
            *(unsigned*)(KH + r * 72 + c)     = hA;
            *(unsigned*)(KH + r * 72 + c + 2) = hB;
            *(unsigned*)(KL + r * 72 + c)     = lA;
            *(unsigned*)(KL + r * 72 + c + 2) = lB;
            float4 vv = *(const float4*)(vp + (size_t)r * DMODEL + c);
            bfsplit2(vv.x, vv.y, hA, lA);
            bfsplit2(vv.z, vv.w, hB, lB);
            *(unsigned*)(VH + r * 72 + c)     = hA;
            *(unsigned*)(VH + r * 72 + c + 2) = hB;
            *(unsigned*)(VL + r * 72 + c)     = lA;
            *(unsigned*)(VL + r * 72 + c + 2) = lB;
        }
        __syncthreads();

        // ---- S = Q K^T (3-term bf16) ----
        float s[8][4];
        #pragma unroll
        for (int nt = 0; nt < 8; nt++)
            #pragma unroll
            for (int i = 0; i < 4; i++) s[nt][i] = 0.f;

        #pragma unroll
        for (int ks = 0; ks < 4; ks++) {
            const int k = ks * 16;
            #pragma unroll
            for (int nt = 0; nt < 8; nt++) {
                int n = nt * 8 + qr;
                unsigned bh[2], bl[2];
                bh[0] = *(const unsigned*)(KH + n * 72 + k + 2 * qc);
                bh[1] = *(const unsigned*)(KH + n * 72 + k + 8 + 2 * qc);
                bl[0] = *(const unsigned*)(KL + n * 72 + k + 2 * qc);
                bl[1] = *(const unsigned*)(KL + n * 72 + k + 8 + 2 * qc);
                mma_bf16(s[nt], qhi[ks], bh);
                mma_bf16(s[nt], qhi[ks], bl);
                mma_bf16(s[nt], qlo[ks], bh);
            }
        }

        // ---- scale + causal mask + row max ----
        float mx0 = m0, mx1 = m1;
        #pragma unroll
        for (int nt = 0; nt < 8; nt++) {
            int cg = kj * 64 + nt * 8 + 2 * qc;
            #pragma unroll
            for (int d = 0; d < 2; d++) {
                float v0 = s[nt][d] * 0.125f;
                if (cg + d > rowg0) v0 = -1e30f;
                s[nt][d] = v0; mx0 = fmaxf(mx0, v0);
                float v1 = s[nt][2 + d] * 0.125f;
                if (cg + d > rowg1) v1 = -1e30f;
                s[nt][2 + d] = v1; mx1 = fmaxf(mx1, v1);
            }
        }
        mx0 = fmaxf(mx0, __shfl_xor_sync(0xffffffffu, mx0, 1));
        mx0 = fmaxf(mx0, __shfl_xor_sync(0xffffffffu, mx0, 2));
        mx1 = fmaxf(mx1, __shfl_xor_sync(0xffffffffu, mx1, 1));
        mx1 = fmaxf(mx1, __shfl_xor_sync(0xffffffffu, mx1, 2));

        float a0 = __expf(m0 - mx0);
        float a1 = __expf(m1 - mx1);
        m0 = mx0; m1 = mx1;

        float rs0 = 0.f, rs1 = 0.f;
        #pragma unroll
        for (int nt = 0; nt < 8; nt++) {
            float p0 = __expf(s[nt][0] - mx0), p1 = __expf(s[nt][1] - mx0);
            float p2 = __expf(s[nt][2] - mx1), p3 = __expf(s[nt][3] - mx1);
            rs0 += p0 + p1; rs1 += p2 + p3;
            unsigned hh, ll;
            bfsplit2(p0, p1, hh, ll);
            *(unsigned*)(PH + rm * 72 + nt * 8 + 2 * qc) = hh;
            *(unsigned*)(PL + rm * 72 + nt * 8 + 2 * qc) = ll;
            bfsplit2(p2, p3, hh, ll);
            *(unsigned*)(PH + (rm + 8) * 72 + nt * 8 + 2 * qc) = hh;
            *(unsigned*)(PL + (rm + 8) * 72 + nt * 8 + 2 * qc) = ll;
        }
        rs0 += __shfl_xor_sync(0xffffffffu, rs0, 1);
        rs0 += __shfl_xor_sync(0xffffffffu, rs0, 2);
        rs1 += __shfl_xor_sync(0xffffffffu, rs1, 1);
        rs1 += __shfl_xor_sync(0xffffffffu, rs1, 2);
        l0 = l0 * a0 + rs0;
        l1 = l1 * a1 + rs1;

        #pragma unroll
        for (int nt = 0; nt < 8; nt++) {
            o[nt][0] *= a0; o[nt][1] *= a0;
            o[nt][2] *= a1; o[nt][3] *= a1;
        }
        __syncwarp();   // P rows written per-warp; each warp reads only its own rows

        // ---- O += P V (3-term bf16, V frags via ldmatrix.trans) ----
        #pragma unroll
        for (int ks = 0; ks < 4; ks++) {
            const int k = ks * 16;
            unsigned ah[4], al[4];
            ah[0] = *(const unsigned*)(PH + rm * 72 + k + 2 * qc);
            ah[1] = *(const unsigned*)(PH + (rm + 8) * 72 + k + 2 * qc);
            ah[2] = *(const unsigned*)(PH + rm * 72 + k + 8 + 2 * qc);
            ah[3] = *(const unsigned*)(PH + (rm + 8) * 72 + k + 8 + 2 * qc);
            al[0] = *(const unsigned*)(PL + rm * 72 + k + 2 * qc);
            al[1] = *(const unsigned*)(PL + (rm + 8) * 72 + k + 2 * qc);
            al[2] = *(const unsigned*)(PL + rm * 72 + k + 8 + 2 * qc);
            al[3] = *(const unsigned*)(PL + (rm + 8) * 72 + k + 8 + 2 * qc);
            const uint32_t rowOff = (uint32_t)((k + l15) * 72) * 2u;
            #pragma unroll
            for (int nt = 0; nt < 8; nt++) {
                unsigned bh[2], bl[2];
                ldmx2t(bh[0], bh[1], vhb + rowOff + (uint32_t)(nt * 8) * 2u);
                ldmx2t(bl[0], bl[1], vlb + rowOff + (uint32_t)(nt * 8) * 2u);
                mma_bf16(o[nt], ah, bh);
                mma_bf16(o[nt], ah, bl);
                mma_bf16(o[nt], al, bh);
            }
        }
        __syncthreads();   // K/V reads done before next tile staging
    }

    // ---- normalize + write O (fp32) ----
    float inv0 = 1.0f / l0, inv1 = 1.0f / l1;
    float* op = O + rowQ0 * DMODEL + hoff;
    #pragma unroll
    for (int nt = 0; nt < 8; nt++) {
        int c = nt * 8 + 2 * qc;
        *(float2*)(op + (size_t)rm * DMODEL + c)       = make_float2(o[nt][0] * inv0, o[nt][1] * inv0);
        *(float2*)(op + (size_t)(rm + 8) * DMODEL + c) = make_float2(o[nt][2] * inv1, o[nt][3] * inv1);
    }
}

// ---------------------------------------------------------------------------
// Launch
// ---------------------------------------------------------------------------
extern "C" void kernel_launch(void* const* d_in, const int* in_sizes, int n_in,
                              void* d_out, int out_size)
{
    const float* hidden = (const float*)d_in[0];
    const float* cosT   = (const float*)d_in[1];
    const float* sinT   = (const float*)d_in[2];
    // d_in[3] = attention_mask (pure causal; reproduced analytically)
    const float* Wq     = (const float*)d_in[4];
    const float* Wk     = (const float*)d_in[5];
    const float* Wv     = (const float*)d_in[6];
    const float* Wo     = (const float*)d_in[7];
    float* out = (float*)d_out;

    float *Qp, *Kp, *Vp, *Op;
    cudaGetSymbolAddress((void**)&Qp, g_Q);
    cudaGetSymbolAddress((void**)&Kp, g_K);
    cudaGetSymbolAddress((void**)&Vp, g_V);
    cudaGetSymbolAddress((void**)&Op, g_O);

    cudaFuncSetAttribute(gemm_tf32, cudaFuncAttributeMaxDynamicSharedMemorySize, GEMM_SMEM);
    cudaFuncSetAttribute(attn_mma,  cudaFuncAttributeMaxDynamicSharedMemorySize, ATTN_SMEM);

    dim3 gg(DMODEL / 128, MTOT / 128);   // (8, 32)

    gemm_tf32<<<gg, 256, GEMM_SMEM>>>(hidden, Wq, Qp, MTOT, DMODEL, DMODEL);
    gemm_tf32<<<gg, 256, GEMM_SMEM>>>(hidden, Wk, Kp, MTOT, DMODEL, DMODEL);
    gemm_tf32<<<gg, 256, GEMM_SMEM>>>(hidden, Wv, Vp, MTOT, DMODEL, DMODEL);

    rope_kernel<<<(MTOT * NHEADS * 32) / 256, 256>>>(Qp, Kp, cosT, sinT);

    attn_mma<<<dim3(SEQ / 128, NHEADS, BATCH), 256, ATTN_SMEM>>>(Qp, Kp, Vp, Op);

    gemm_tf32<<<gg, 256, GEMM_SMEM>>>(Op, Wo, out, MTOT, DMODEL, DMODEL);
}

// round 14
// speedup vs baseline: 1.8031x; 1.1211x over previous
#include <cuda_runtime.h>
#include <cuda_bf16.h>
#include <math.h>
#include <stdint.h>

#define BATCH   2
#define SEQ     2048
#define DMODEL  1024
#define NHEADS  16
#define DHEAD   64
#define MTOT    (BATCH*SEQ)   // 4096
#define NELEM   (MTOT*DMODEL)

// Scratch (allocation-free rule: __device__ globals)
__device__ float g_A[NELEM];            // tf32-rounded hidden
__device__ float g_Q[NELEM];
__device__ float g_K[NELEM];
__device__ float g_V[NELEM];
__device__ float g_O[NELEM];            // attention output, tf32-pre-rounded
__device__ float g_WT[3072*1024];       // [n][k] tf32-rounded fused Wq|Wk|Wv
__device__ float g_WoT[1024*1024];      // [n][k] tf32-rounded Wo

__device__ __forceinline__ float tf32r(float x) {
    asm("cvt.rna.tf32.f32 %0, %0;" : "+f"(x));
    return x;
}

__device__ __forceinline__ void mma_tf32(float c[4], const unsigned a[4], const unsigned b[2]) {
    asm volatile(
        "mma.sync.aligned.m16n8k8.row.col.f32.tf32.tf32.f32 "
        "{%0,%1,%2,%3}, {%4,%5,%6,%7}, {%8,%9}, {%0,%1,%2,%3};\n"
        : "+f"(c[0]), "+f"(c[1]), "+f"(c[2]), "+f"(c[3])
        : "r"(a[0]), "r"(a[1]), "r"(a[2]), "r"(a[3]), "r"(b[0]), "r"(b[1]));
}
__device__ __forceinline__ void mma_bf16(float c[4], const unsigned a[4], const unsigned b[2]) {
    asm volatile(
        "mma.sync.aligned.m16n8k16.row.col.f32.bf16.bf16.f32 "
        "{%0,%1,%2,%3}, {%4,%5,%6,%7}, {%8,%9}, {%0,%1,%2,%3};\n"
        : "+f"(c[0]), "+f"(c[1]), "+f"(c[2]), "+f"(c[3])
        : "r"(a[0]), "r"(a[1]), "r"(a[2]), "r"(a[3]), "r"(b[0]), "r"(b[1]));
}
__device__ __forceinline__ void ldmx4(unsigned &d0, unsigned &d1, unsigned &d2, unsigned &d3,
                                      uint32_t addr) {
    asm volatile("ldmatrix.sync.aligned.m8n8.x4.shared.b16 {%0,%1,%2,%3}, [%4];"
                 : "=r"(d0), "=r"(d1), "=r"(d2), "=r"(d3) : "r"(addr));
}
__device__ __forceinline__ void ldmx2(unsigned &d0, unsigned &d1, uint32_t addr) {
    asm volatile("ldmatrix.sync.aligned.m8n8.x2.shared.b16 {%0,%1}, [%2];"
                 : "=r"(d0), "=r"(d1) : "r"(addr));
}
__device__ __forceinline__ void ldmx2t(unsigned &d0, unsigned &d1, uint32_t addr) {
    asm volatile("ldmatrix.sync.aligned.m8n8.x2.trans.shared.b16 {%0,%1}, [%2];"
                 : "=r"(d0), "=r"(d1) : "r"(addr));
}
__device__ __forceinline__ unsigned bfpack(float a, float b) {
    __nv_bfloat162 h = __floats2bfloat162_rn(a, b);
    return *reinterpret_cast<unsigned*>(&h);
}
__device__ __forceinline__ void bfsplit2(float a, float b, unsigned &hi, unsigned &lo) {
    float ha = __bfloat162float(__float2bfloat16_rn(a));
    float hb = __bfloat162float(__float2bfloat16_rn(b));
    hi = bfpack(ha, hb);
    lo = bfpack(a - ha, b - hb);
}
__device__ __forceinline__ void cp_async16(uint32_t dst, const void* src) {
    asm volatile("cp.async.cg.shared.global [%0], [%1], 16;" :: "r"(dst), "l"(src));
}

// ---------------------------------------------------------------------------
// prep_round: g_A = tf32r(hidden), float4 per thread.
// ---------------------------------------------------------------------------
__global__ void prep_round(const float* __restrict__ H, float* __restrict__ A)
{
    int i = blockIdx.x * blockDim.x + threadIdx.x;   // [0, NELEM/4)
    float4 v = ((const float4*)H)[i];
    v.x = tf32r(v.x); v.y = tf32r(v.y); v.z = tf32r(v.z); v.w = tf32r(v.w);
    ((float4*)A)[i] = v;
}

// ---------------------------------------------------------------------------
// prep_weights: transpose [k][n] -> [n][k] with tf32 rounding.
// blockIdx.z: 0,1,2 = Wq,Wk,Wv -> g_WT (fused rows n = which*1024 + n_local); 3 = Wo -> g_WoT
// ---------------------------------------------------------------------------
__global__ void prep_weights(const float* __restrict__ Wq, const float* __restrict__ Wk,
                             const float* __restrict__ Wv, const float* __restrict__ Wo,
                             float* __restrict__ WT, float* __restrict__ WoT)
{
    __shared__ float t[32][33];
    int which = blockIdx.z;
    const float* W = (which == 0) ? Wq : (which == 1) ? Wk : (which == 2) ? Wv : Wo;
    int n0 = blockIdx.x * 32, k0 = blockIdx.y * 32;
    #pragma unroll
    for (int i = 0; i < 32; i += 8)
        t[threadIdx.y + i][threadIdx.x] = W[(size_t)(k0 + threadIdx.y + i) * 1024 + n0 + threadIdx.x];
    __syncthreads();
    float* dst = (which < 3) ? (WT + (size_t)which * 1024 * 1024) : WoT;
    #pragma unroll
    for (int i = 0; i < 32; i += 8)
        dst[(size_t)(n0 + threadIdx.y + i) * 1024 + k0 + threadIdx.x] =
            tf32r(t[threadIdx.x][threadIdx.y + i]);
}

// ---------------------------------------------------------------------------
// TF32 GEMM with ldmatrix fragments, pre-rounded operands.
// A [M][K] row-major, BT [N][K] row-major (B transposed). 128x128x32 tile,
// 8 warps, cp.async double-buffered. No cvt in the loop.
// Smem per buf: A[128][36] + BT[128][36] floats = 36864 B; x2 = 73728 B.
// QKV=true: N=3072, epilogue routes cols to Qo/Ko/Vo (each [M][1024]).
// ---------------------------------------------------------------------------
#define GEMM_SMEM 73728

template<bool QKV>
__global__ __launch_bounds__(256, 2)
void gemm_ldm(const float* __restrict__ A, const float* __restrict__ BT,
              float* __restrict__ C, float* __restrict__ Qo, float* __restrict__ Ko,
              float* __restrict__ Vo, int M, int N, int K)
{
    extern __shared__ float gsm[];

    const int tid  = threadIdx.x;
    const int lane = tid & 31;
    const int warp = tid >> 5;
    const int rowW = (warp >> 2) * 64;
    const int colW = (warp & 3) * 32;
    const int qr   = lane >> 2;
    const int qc   = lane & 3;
    const int lr   = lane & 7;

    const int rowBase = blockIdx.y * 128;
    const int colBase = blockIdx.x * 128;

    const uint32_t sbase = (uint32_t)__cvta_generic_to_shared(gsm);

    // ldmatrix per-lane base offsets (bytes), within current buffer
    const uint32_t aLane = (uint32_t)(((rowW + ((lane >> 3) & 1) * 8 + lr) * 36
                                       + (lane >> 4) * 4) * 4);
    const uint32_t bLane = (uint32_t)(((colW + lr) * 36
                                       + ((lane >> 3) & 1) * 4) * 4) + 18432u;

    const int rS = tid >> 3, cS = (tid & 7) << 2;

    auto stage = [&](int buf, int k0) {
        uint32_t ab  = sbase + (uint32_t)buf * 36864u;
        uint32_t btb = ab + 18432u;
        #pragma unroll
        for (int l = 0; l < 4; l++) {
            int rr = rS + 32 * l;
            cp_async16(ab  + (uint32_t)((rr * 36 + cS) * 4),
                       A  + (size_t)(rowBase + rr) * K + k0 + cS);
            cp_async16(btb + (uint32_t)((rr * 36 + cS) * 4),
                       BT + (size_t)(colBase + rr) * K + k0 + cS);
        }
        asm volatile("cp.async.commit_group;");
    };

    float acc[4][4][4];
    #pragma unroll
    for (int mt = 0; mt < 4; mt++)
        #pragma unroll
        for (int nt = 0; nt < 4; nt++)
            #pragma unroll
            for (int i = 0; i < 4; i++) acc[mt][nt][i] = 0.f;

    stage(0, 0);
    int buf = 0;
    for (int k0 = 0; k0 < K; k0 += 32) {
        asm volatile("cp.async.wait_group 0;");
        __syncthreads();
        if (k0 + 32 < K) stage(buf ^ 1, k0 + 32);

        const uint32_t bb = sbase + (uint32_t)buf * 36864u;

        #pragma unroll
        for (int kk = 0; kk < 4; kk++) {
            unsigned b[4][2];
            #pragma unroll
            for (int nt = 0; nt < 4; nt++)
                ldmx2(b[nt][0], b[nt][1],
                      bb + bLane + (uint32_t)((nt * 8 * 36 + kk * 8) * 4));
            #pragma unroll
            for (int mt = 0; mt < 4; mt++) {
                unsigned a[4];
                ldmx4(a[0], a[1], a[2], a[3],
                      bb + aLane + (uint32_t)((mt * 16 * 36 + kk * 8) * 4));
                #pragma unroll
                for (int nt = 0; nt < 4; nt++)
                    mma_tf32(acc[mt][nt], a, b[nt]);
            }
        }
        buf ^= 1;
    }

    #pragma unroll
    for (int mt = 0; mt < 4; mt++) {
        int r = rowBase + rowW + mt * 16 + qr;
        #pragma unroll
        for (int nt = 0; nt < 4; nt++) {
            int cg = colBase + colW + nt * 8 + 2 * qc;
            float2 v0 = make_float2(acc[mt][nt][0], acc[mt][nt][1]);
            float2 v1 = make_float2(acc[mt][nt][2], acc[mt][nt][3]);
            if (QKV) {
                float* dst; int c;
                if (cg < 1024)      { dst = Qo; c = cg; }
                else if (cg < 2048) { dst = Ko; c = cg - 1024; }
                else                { dst = Vo; c = cg - 2048; }
                *(float2*)(dst + (size_t)r * 1024 + c)       = v0;
                *(float2*)(dst + (size_t)(r + 8) * 1024 + c) = v1;
            } else {
                *(float2*)(C + (size_t)r * N + cg)       = v0;
                *(float2*)(C + (size_t)(r + 8) * N + cg) = v1;
            }
        }
    }
}

// ---------------------------------------------------------------------------
// RoPE in-place (proven).
// ---------------------------------------------------------------------------
__global__ void rope_kernel(float* __restrict__ Q, float* __restrict__ K,
                            const float* __restrict__ cosT,
                            const float* __restrict__ sinT)
{
    int idx = blockIdx.x * blockDim.x + threadIdx.x;
    int d  = idx & 31;
    int h  = (idx >> 5) & (NHEADS - 1);
    int ms = idx >> 9;
    int s  = ms & (SEQ - 1);

    float c  = cosT[s * 32 + d];
    float sn = sinT[s * 32 + d];
    size_t base = (size_t)ms * DMODEL + h * DHEAD + d;

    float x1 = Q[base], x2 = Q[base + 32];
    Q[base]      = x1 * c - x2 * sn;
    Q[base + 32] = x2 * c + x1 * sn;

    float y1 = K[base], y2 = K[base + 32];
    K[base]      = y1 * c - y2 * sn;
    K[base + 32] = y2 * c + y1 * sn;
}

// ---------------------------------------------------------------------------
// Flash attention: bf16 3-term split (R5-proven config: 64 q-rows, 4 warps).
// Epilogue stores O pre-rounded to tf32 for the Wo GEMM.
// ---------------------------------------------------------------------------
#define ATTN_SMEM (4 * 4608 * 2)

__global__ __launch_bounds__(128, 4)
void attn_mma(const float* __restrict__ Q, const float* __restrict__ K,
              const float* __restrict__ V, float* __restrict__ O)
{
    extern __shared__ __nv_bfloat16 smb[];
    __nv_bfloat16* KH = smb;               // [64][72]   (later PH)
    __nv_bfloat16* KL = smb + 4608;        // [64][72]   (later PL)
    __nv_bfloat16* VH = smb + 2 * 4608;
    __nv_bfloat16* VL = smb + 3 * 4608;

    const uint32_t vhb = (uint32_t)__cvta_generic_to_shared(VH);
    const uint32_t vlb = (uint32_t)__cvta_generic_to_shared(VL);

    const int qb = blockIdx.x, h = blockIdx.y, b = blockIdx.z;
    const int tid = threadIdx.x;
    const int lane = tid & 31, w = tid >> 5;
    const int qr = lane >> 2, qc = lane & 3;
    const int rm = w * 16 + qr;
    const int l15 = lane & 15;

    const size_t hoff = (size_t)h * DHEAD;
    const size_t rowQ0 = (size_t)b * SEQ + (size_t)qb * 64;

    unsigned qhi[4][4], qlo[4][4];
    {
        const float* qp = Q + rowQ0 * DMODEL + hoff;
        #pragma unroll
        for (int ks = 0; ks < 4; ks++) {
            int k = ks * 16;
            float2 t;
            t = *(const float2*)(qp + (size_t)rm * DMODEL + k + 2 * qc);
            bfsplit2(t.x, t.y, qhi[ks][0], qlo[ks][0]);
            t = *(const float2*)(qp + (size_t)(rm + 8) * DMODEL + k + 2 * qc);
            bfsplit2(t.x, t.y, qhi[ks][1], qlo[ks][1]);
            t = *(const float2*)(qp + (size_t)rm * DMODEL + k + 8 + 2 * qc);
            bfsplit2(t.x, t.y, qhi[ks][2], qlo[ks][2]);
            t = *(const float2*)(qp + (size_t)(rm + 8) * DMODEL + k + 8 + 2 * qc);
            bfsplit2(t.x, t.y, qhi[ks][3], qlo[ks][3]);
        }
    }

    float o[8][4];
    #pragma unroll
    for (int nt = 0; nt < 8; nt++)
        #pragma unroll
        for (int i = 0; i < 4; i++) o[nt][i] = 0.f;
    float m0 = -3.0e38f, m1 = -3.0e38f, l0 = 0.f, l1 = 0.f;

    const int rowg0 = qb * 64 + rm;
    const int rowg1 = rowg0 + 8;

    for (int kj = 0; kj <= qb; kj++) {
        const float* kp = K + ((size_t)b * SEQ + (size_t)kj * 64) * DMODEL + hoff;
        const float* vp = V + ((size_t)b * SEQ + (size_t)kj * 64) * DMODEL + hoff;
        #pragma unroll
        for (int l = 0; l < 8; l++) {
            int idx = tid + l * 128;
            int r = idx >> 4, c = (idx & 15) << 2;
            float4 kv = *(const float4*)(kp + (size_t)r * DMODEL + c);
            unsigned hA, lA, hB, lB;
            bfsplit2(kv.x, kv.y, hA, lA);
            bfsplit2(kv.z, kv.w, hB, lB);
            *(unsigned*)(KH + r * 72 + c)     = hA;
            *(unsigned*)(KH + r * 72 + c + 2) = hB;
            *(unsigned*)(KL + r * 72 + c)     = lA;
            *(unsigned*)(KL + r * 72 + c + 2) = lB;
            float4 vv = *(const float4*)(vp + (size_t)r * DMODEL + c);
            bfsplit2(vv.x, vv.y, hA, lA);
            bfsplit2(vv.z, vv.w, hB, lB);
            *(unsigned*)(VH + r * 72 + c)     = hA;
            *(unsigned*)(VH + r * 72 + c + 2) = hB;
            *(unsigned*)(VL + r * 72 + c)     = lA;
            *(unsigned*)(VL + r * 72 + c + 2) = lB;
        }
        __syncthreads();

        float s[8][4];
        #pragma unroll
        for (int nt = 0; nt < 8; nt++)
            #pragma unroll
            for (int i = 0; i < 4; i++) s[nt][i] = 0.f;

        #pragma unroll
        for (int ks = 0; ks < 4; ks++) {
            const int k = ks * 16;
            #pragma unroll
            for (int nt = 0; nt < 8; nt++) {
                int n = nt * 8 + qr;
                unsigned bh[2], bl[2];
                bh[0] = *(const unsigned*)(KH + n * 72 + k + 2 * qc);
                bh[1] = *(const unsigned*)(KH + n * 72 + k + 8 + 2 * qc);
                bl[0] = *(const unsigned*)(KL + n * 72 + k + 2 * qc);
                bl[1] = *(const unsigned*)(KL + n * 72 + k + 8 + 2 * qc);
                mma_bf16(s[nt], qhi[ks], bh);
                mma_bf16(s[nt], qhi[ks], bl);
                mma_bf16(s[nt], qlo[ks], bh);
            }
        }
        __syncthreads();   // K reads done; KH/KL become PH/PL

        float mx0 = m0, mx1 = m1;
        #pragma unroll
        for (int nt = 0; nt < 8; nt++) {
            int cg = kj * 64 + nt * 8 + 2 * qc;
            #pragma unroll
            for (int d = 0; d < 2; d++) {
                float v0 = s[nt][d] * 0.125f;
                if (cg + d > rowg0) v0 = -1e30f;
                s[nt][d] = v0; mx0 = fmaxf(mx0, v0);
                float v1 = s[nt][2 + d] * 0.125f;
                if (cg + d > rowg1) v1 = -1e30f;
                s[nt][2 + d] = v1; mx1 = fmaxf(mx1, v1);
            }
        }
        mx0 = fmaxf(mx0, __shfl_xor_sync(0xffffffffu, mx0, 1));
        mx0 = fmaxf(mx0, __shfl_xor_sync(0xffffffffu, mx0, 2));
        mx1 = fmaxf(mx1, __shfl_xor_sync(0xffffffffu, mx1, 1));
        mx1 = fmaxf(mx1, __shfl_xor_sync(0xffffffffu, mx1, 2));

        float a0 = __expf(m0 - mx0);
        float a1 = __expf(m1 - mx1);
        m0 = mx0; m1 = mx1;

        float rs0 = 0.f, rs1 = 0.f;
        #pragma unroll
        for (int nt = 0; nt < 8; nt++) {
            float p0 = __expf(s[nt][0] - mx0), p1 = __expf(s[nt][1] - mx0);
            float p2 = __expf(s[nt][2] - mx1), p3 = __expf(s[nt][3] - mx1);
            rs0 += p0 + p1; rs1 += p2 + p3;
            unsigned hh, ll;
            bfsplit2(p0, p1, hh, ll);
            *(unsigned*)(KH + rm * 72 + nt * 8 + 2 * qc) = hh;
            *(unsigned*)(KL + rm * 72 + nt * 8 + 2 * qc) = ll;
            bfsplit2(p2, p3, hh, ll);
            *(unsigned*)(KH + (rm + 8) * 72 + nt * 8 + 2 * qc) = hh;
            *(unsigned*)(KL + (rm + 8) * 72 + nt * 8 + 2 * qc) = ll;
        }
        rs0 += __shfl_xor_sync(0xffffffffu, rs0, 1);
        rs0 += __shfl_xor_sync(0xffffffffu, rs0, 2);
        rs1 += __shfl_xor_sync(0xffffffffu, rs1, 1);
        rs1 += __shfl_xor_sync(0xffffffffu, rs1, 2);
        l0 = l0 * a0 + rs0;
        l1 = l1 * a1 + rs1;

        #pragma unroll
        for (int nt = 0; nt < 8; nt++) {
            o[nt][0] *= a0; o[nt][1] *= a0;
            o[nt][2] *= a1; o[nt][3] *= a1;
        }
        __syncthreads();

        #pragma unroll
        for (int ks = 0; ks < 4; ks++) {
            const int k = ks * 16;
            unsigned ah[4], al[4];
            ah[0] = *(const unsigned*)(KH + rm * 72 + k + 2 * qc);
            ah[1] = *(const unsigned*)(KH + (rm + 8) * 72 + k + 2 * qc);
            ah[2] = *(const unsigned*)(KH + rm * 72 + k + 8 + 2 * qc);
            ah[3] = *(const unsigned*)(KH + (rm + 8) * 72 + k + 8 + 2 * qc);
            al[0] = *(const unsigned*)(KL + rm * 72 + k + 2 * qc);
            al[1] = *(const unsigned*)(KL + (rm + 8) * 72 + k + 2 * qc);
            al[2] = *(const unsigned*)(KL + rm * 72 + k + 8 + 2 * qc);
            al[3] = *(const unsigned*)(KL + (rm + 8) * 72 + k + 8 + 2 * qc);
            const uint32_t rowOff = (uint32_t)((k + l15) * 72) * 2u;
            #pragma unroll
            for (int nt = 0; nt < 8; nt++) {
                unsigned bh[2], bl[2];
                ldmx2t(bh[0], bh[1], vhb + rowOff + (uint32_t)(nt * 8) * 2u);
                ldmx2t(bl[0], bl[1], vlb + rowOff + (uint32_t)(nt * 8) * 2u);
                mma_bf16(o[nt], ah, bh);
                mma_bf16(o[nt], ah, bl);
                mma_bf16(o[nt], al, bh);
            }
        }
        __syncthreads();
    }

    // normalize + write O, pre-rounded to tf32 for the Wo GEMM
    float inv0 = 1.0f / l0, inv1 = 1.0f / l1;
    float* op = O + rowQ0 * DMODEL + hoff;
    #pragma unroll
    for (int nt = 0; nt < 8; nt++) {
        int c = nt * 8 + 2 * qc;
        *(float2*)(op + (size_t)rm * DMODEL + c) =
            make_float2(tf32r(o[nt][0] * inv0), tf32r(o[nt][1] * inv0));
        *(float2*)(op + (size_t)(rm + 8) * DMODEL + c) =
            make_float2(tf32r(o[nt][2] * inv1), tf32r(o[nt][3] * inv1));
    }
}

// ---------------------------------------------------------------------------
// Launch
// ---------------------------------------------------------------------------
extern "C" void kernel_launch(void* const* d_in, const int* in_sizes, int n_in,
                              void* d_out, int out_size)
{
    const float* hidden = (const float*)d_in[0];
    const float* cosT   = (const float*)d_in[1];
    const float* sinT   = (const float*)d_in[2];
    // d_in[3] = attention_mask (pure causal; reproduced analytically)
    const float* Wq     = (const float*)d_in[4];
    const float* Wk     = (const float*)d_in[5];
    const float* Wv     = (const float*)d_in[6];
    const float* Wo     = (const float*)d_in[7];
    float* out = (float*)d_out;

    float *Ap, *Qp, *Kp, *Vp, *Op, *WTp, *WoTp;
    cudaGetSymbolAddress((void**)&Ap,  g_A);
    cudaGetSymbolAddress((void**)&Qp,  g_Q);
    cudaGetSymbolAddress((void**)&Kp,  g_K);
    cudaGetSymbolAddress((void**)&Vp,  g_V);
    cudaGetSymbolAddress((void**)&Op,  g_O);
    cudaGetSymbolAddress((void**)&WTp, g_WT);
    cudaGetSymbolAddress((void**)&WoTp, g_WoT);

    cudaFuncSetAttribute(gemm_ldm<true>,  cudaFuncAttributeMaxDynamicSharedMemorySize, GEMM_SMEM);
    cudaFuncSetAttribute(gemm_ldm<false>, cudaFuncAttributeMaxDynamicSharedMemorySize, GEMM_SMEM);
    cudaFuncSetAttribute(attn_mma,        cudaFuncAttributeMaxDynamicSharedMemorySize, ATTN_SMEM);

    prep_round<<<NELEM / 4 / 256, 256>>>(hidden, Ap);
    prep_weights<<<dim3(32, 32, 4), dim3(32, 8)>>>(Wq, Wk, Wv, Wo, WTp, WoTp);

    gemm_ldm<true><<<dim3(24, 32), 256, GEMM_SMEM>>>(
        Ap, WTp, nullptr, Qp, Kp, Vp, MTOT, 3072, 1024);

    rope_kernel<<<(MTOT * NHEADS * 32) / 256, 256>>>(Qp, Kp, cosT, sinT);

    attn_mma<<<dim3(SEQ / 64, NHEADS, BATCH), 128, ATTN_SMEM>>>(Qp, Kp, Vp, Op);

    gemm_ldm<false><<<dim3(8, 32), 256, GEMM_SMEM>>>(
        Op, WoTp, out, nullptr, nullptr, nullptr, MTOT, 1024, 1024);
}